// round 16
// baseline (speedup 1.0000x reference)
#include <cuda_runtime.h>
#include <cuda_fp16.h>

// ---------------------------------------------------------------------------
// N=512, MAX_DIST=16, H=32, N_SPATIAL=64, BOND_TYPES=32.
// edge_sum[i,j,k] = sum_d T[d][edge_input[i,j,d]][k],  T[d] = edge_table @ W[d]
// R16: pack stage ELIMINATED. Kernel 1 = T precompute only (16 blocks).
// Kernel 2 (persistent, 888 = 6/SM x 148, work stealing):
//   tasks 0..511    : phi_spd (512-pair slice, 2 pairs/thread, fp16 shS,
//                     STG.64) — placed FIRST so the tail stays fine-grained
//   tasks 512..4607 : phi_edge, R12 loop, but indices loaded RAW from
//                     edge_input per d-group (4 LDG.128/warp-task; kills the
//                     entire pack kernel + 20MB traffic + one launch gap)
// ---------------------------------------------------------------------------

#define NN        512
#define PAIRS     (NN * NN)          // 262144
#define MAXD      16
#define H         32
#define NSPAT     64
#define T2_ELEMS  (MAXD * 16 * 32)   // 8192 half2 = 32KB
#define SHS_ELEMS (16 * NSPAT)       // 1024 half2 = 4KB
#define SMEM_BYTES ((T2_ELEMS + SHS_ELEMS) * 4)   // 36864 -> 6 blocks/SM
#define GRID      888               // 6 blocks/SM * 148 SMs
#define N_SPD_TASKS  512            // 512-pair tiles, all 32 heads
#define N_EDGE_TASKS 4096           // 1024 tiles(256 pairs) * 4 k-quarters
#define N_TASKS   (N_SPD_TASKS + N_EDGE_TASKS)   // 4608

__device__ __half2   g_T2[T2_ELEMS];   // [d][k2][e]
__device__ unsigned  g_task_counter;

// Kernel 1: T[d] = edge_table @ W[d] (one block per d) + counter reset.
__global__ __launch_bounds__(256)
void prep_T_kernel(const float* __restrict__ edge_table,
                   const float* __restrict__ W) {
    __shared__ float shBuf[2048];
    int t = threadIdx.x;
    if (blockIdx.x == 0 && t == 0) g_task_counter = 0u;

    float* shE = shBuf;            // [h][e]
    float* shW = shBuf + H * H;    // [h][k]
    int d = blockIdx.x;
    for (int i = t; i < H * H; i += 256) {
        int e = i >> 5, h = i & 31;
        shE[h * H + e] = edge_table[i];
        shW[i] = W[d * (H * H) + i];
    }
    __syncthreads();
    int e = t & 31;
#pragma unroll
    for (int rep = 0; rep < 2; ++rep) {
        int k2 = (t >> 5) + 8 * rep;
        float s0 = 0.0f, s1 = 0.0f;
#pragma unroll
        for (int h = 0; h < H; ++h) {
            float ev = shE[h * H + e];          // bank = e, conflict-free
            s0 += ev * shW[h * H + 2 * k2];     // broadcast
            s1 += ev * shW[h * H + 2 * k2 + 1];
        }
        g_T2[d * 512 + k2 * 32 + e] = __floats2half2_rn(s0, s1);
    }
}

// Kernel 2: everything else.
__global__ __launch_bounds__(256, 6)
void bond_encoding_kernel(const int* __restrict__ spatial_pos,
                          const int* __restrict__ edge_input,
                          const float* __restrict__ spd_table,
                          float* __restrict__ out) {
    extern __shared__ float sh[];
    __half2* shT = (__half2*)sh;              // [d][k2][e], 32KB
    __half2* shS = (__half2*)sh + T2_ELEMS;   // [k2][sp],   4KB
    __shared__ int mail[2];
    const int t = threadIdx.x;

    {
        const float4* src = (const float4*)g_T2;
        float4* dst = (float4*)sh;
#pragma unroll
        for (int i = t; i < T2_ELEMS / 4; i += 256)
            dst[i] = src[i];
    }
    for (int i = t; i < SHS_ELEMS; i += 256) {
        int k2 = i >> 6;
        int sp = i & 63;
        shS[i] = __floats2half2_rn(spd_table[sp * H + 2 * k2],
                                   spd_table[sp * H + 2 * k2 + 1]);
    }
    if (t == 0) mail[0] = (int)atomicAdd(&g_task_counter, 1u);
    __syncthreads();

    int task = mail[0];
    int slot = 1;
    while (task < N_TASKS) {
        if (t == 0) mail[slot] = (int)atomicAdd(&g_task_counter, 1u);

        if (task < N_SPD_TASKS) {
            // ------- phi_spd task: 512 pairs, all 32 heads, 2 pairs/thread
            int pA = task * 512 + t * 2;
            int2 s = ((const int2*)spatial_pos)[pA >> 1];
#pragma unroll
            for (int k2 = 0; k2 < 16; ++k2) {
                float2 fa = __half22float2(shS[k2 * NSPAT + s.x]);
                float2 fb = __half22float2(shS[k2 * NSPAT + s.y]);
                *(float2*)(out + (2 * k2) * PAIRS + pA)     = make_float2(fa.x, fb.x);
                *(float2*)(out + (2 * k2 + 1) * PAIRS + pA) = make_float2(fa.y, fb.y);
            }
        } else {
            // ------- phi_edge task: 256-pair tile x k-quarter, raw indices
            int et   = task - N_SPD_TASKS;
            int tile = et >> 2;
            int kq   = et & 3;                  // 8 heads
            int pair = tile * 256 + t;

            const uint4* ep = (const uint4*)edge_input + pair * 4;
            int sp = __ldg(spatial_pos + pair);
            float rden = 1.0f / fmaxf((float)sp, 1.0f);

            float acc[8];
#pragma unroll
            for (int j = 0; j < 8; ++j) acc[j] = 0.0f;

#pragma unroll
            for (int g = 0; g < 4; ++g) {       // d-group of 4: d = 4g..4g+3
                uint4 eg = ep[g];               // 4 raw indices (0..31)
                const char* base = (const char*)(shT + ((4 * g) * 16 + kq * 4) * 32);
                const __half2* p0 = (const __half2*)(base          + (eg.x << 2));
                const __half2* p1 = (const __half2*)(base + 2048   + (eg.y << 2));
                const __half2* p2 = (const __half2*)(base + 4096   + (eg.z << 2));
                const __half2* p3 = (const __half2*)(base + 6144   + (eg.w << 2));
#pragma unroll
                for (int j = 0; j < 4; ++j) {   // 4 k2 slots in this quarter
                    __half2 tt = __hadd2(__hadd2(p0[j * 32], p1[j * 32]),
                                         __hadd2(p2[j * 32], p3[j * 32]));
                    float2 f = __half22float2(tt);
                    acc[2 * j]     = fmaf(f.x, rden, acc[2 * j]);
                    acc[2 * j + 1] = fmaf(f.y, rden, acc[2 * j + 1]);
                }
            }

            float* oe = out + (H + kq * 8) * PAIRS + pair;
#pragma unroll
            for (int j = 0; j < 8; ++j)
                oe[j * PAIRS] = acc[j];
        }

        __syncthreads();       // publishes mail[slot]
        task = mail[slot];
        slot ^= 1;
    }
}

extern "C" void kernel_launch(void* const* d_in, const int* in_sizes, int n_in,
                              void* d_out, int out_size) {
    const int*   spatial_pos = nullptr;
    const int*   edge_input  = nullptr;
    const float* spd_table   = nullptr;
    const float* edge_table  = nullptr;
    const float* W           = nullptr;
    for (int i = 0; i < n_in; ++i) {
        switch (in_sizes[i]) {
            case PAIRS:          spatial_pos = (const int*)d_in[i];   break;
            case PAIRS * MAXD:   edge_input  = (const int*)d_in[i];   break;
            case NSPAT * H:      spd_table   = (const float*)d_in[i]; break;
            case H * H:          edge_table  = (const float*)d_in[i]; break;
            case NSPAT * H * H:  W           = (const float*)d_in[i]; break;
            default: break;
        }
    }

    prep_T_kernel<<<MAXD, 256>>>(edge_table, W);

    cudaFuncSetAttribute(bond_encoding_kernel,
                         cudaFuncAttributeMaxDynamicSharedMemorySize, SMEM_BYTES);
    bond_encoding_kernel<<<GRID, 256, SMEM_BYTES>>>(spatial_pos, edge_input,
                                                    spd_table, (float*)d_out);
}

// round 17
// speedup vs baseline: 1.0420x; 1.0420x over previous
#include <cuda_runtime.h>
#include <cuda_fp16.h>

// ---------------------------------------------------------------------------
// N=512, MAX_DIST=16, H=32, N_SPATIAL=64, BOND_TYPES=32.
// edge_sum[i,j,k] = sum_d T[d][edge_input[i,j,d]][k],  T[d] = edge_table @ W[d]
// R17: SINGLE persistent kernel (888 = 6/SM x 148), unified work-stealing
// task space, no global barrier:
//   [0..15]      T-compute (one d per task; smem scratch in shT area)
//   [16..1039]   pack: 256 pairs/task, 1 pair/thread (edge_input -> uint4)
//   [1040..1551] phi_spd: 512 pairs/task, 2 pairs/thread, fp16 shS, STG.64
//   [1552..5647] edge: R12 loop verbatim (gated on g_done == 1040, spin)
// Gate is safe: monotone counter hands out ALL gate tasks before any edge
// task; spd tasks in between hide the gate latency. Counters self-reset at
// exit (last block) -> graph-replay deterministic. Zero launch gaps.
// ---------------------------------------------------------------------------

#define NN        512
#define PAIRS     (NN * NN)          // 262144
#define MAXD      16
#define H         32
#define NSPAT     64
#define T2_ELEMS  (MAXD * 16 * 32)   // 8192 half2 = 32KB
#define SHS_ELEMS (16 * NSPAT)       // 1024 half2 = 4KB
#define SMEM_BYTES ((T2_ELEMS + SHS_ELEMS) * 4)   // 36864 -> 6 blocks/SM
#define GRID      888

#define N_T        16
#define N_PACK     1024              // 256 pairs each
#define N_SPD      512               // 512 pairs each
#define PREP_GATE  (N_T + N_PACK)    // 1040: edge waits for these
#define SPD_BASE   PREP_GATE
#define EDGE_BASE  (PREP_GATE + N_SPD)          // 1552
#define N_EDGE     4096
#define N_TASKS    (EDGE_BASE + N_EDGE)         // 5648

__device__ __half2   g_T2[T2_ELEMS];   // [d][k2][e]
__device__ uint4     g_packed[PAIRS];  // 16 indices, pre-scaled x4, byte each
__device__ unsigned  g_task_counter;   // zero-init; self-reset at exit
__device__ unsigned  g_done;           // completed T+pack tasks
__device__ unsigned  g_exit;           // exited blocks

__global__ __launch_bounds__(256, 6)
void bond_all_kernel(const int* __restrict__ spatial_pos,
                     const int* __restrict__ edge_input,
                     const float* __restrict__ spd_table,
                     const float* __restrict__ edge_table,
                     const float* __restrict__ W,
                     float* __restrict__ out) {
    extern __shared__ float sh[];
    __half2* shT = (__half2*)sh;              // [d][k2][e], 32KB (staged late)
    __half2* shS = (__half2*)sh + T2_ELEMS;   // [k2][sp],   4KB  (staged now)
    __shared__ int mail[2];
    const int t = threadIdx.x;

    // Stage shS (needed by spd tasks; independent of everything else)
    for (int i = t; i < SHS_ELEMS; i += 256) {
        int k2 = i >> 6;
        int sp = i & 63;
        shS[i] = __floats2half2_rn(spd_table[sp * H + 2 * k2],
                                   spd_table[sp * H + 2 * k2 + 1]);
    }
    if (t == 0) mail[0] = (int)atomicAdd(&g_task_counter, 1u);
    __syncthreads();

    int  task   = mail[0];
    int  slot   = 1;
    bool staged = false;

    while (task < N_TASKS) {
        if (t == 0) mail[slot] = (int)atomicAdd(&g_task_counter, 1u);

        if (task < N_T) {
            // ---- T[d] = edge_table @ W[d] (scratch = start of shT area) ----
            float* shE = sh;            // [h][e], 4KB
            float* shW = sh + H * H;    // [h][k], 4KB  (both inside shT area)
            int d = task;
            for (int i = t; i < H * H; i += 256) {
                int e = i >> 5, h = i & 31;
                shE[h * H + e] = edge_table[i];
                shW[i] = W[d * (H * H) + i];
            }
            __syncthreads();
            int e = t & 31;
#pragma unroll
            for (int rep = 0; rep < 2; ++rep) {
                int k2 = (t >> 5) + 8 * rep;
                float s0 = 0.0f, s1 = 0.0f;
#pragma unroll
                for (int h = 0; h < H; ++h) {
                    float ev = shE[h * H + e];          // bank = e
                    s0 += ev * shW[h * H + 2 * k2];     // broadcast
                    s1 += ev * shW[h * H + 2 * k2 + 1];
                }
                g_T2[d * 512 + k2 * 32 + e] = __floats2half2_rn(s0, s1);
            }
            __threadfence();
            __syncthreads();
            if (t == 0) atomicAdd(&g_done, 1u);
        } else if (task < PREP_GATE) {
            // ---- pack: 256 pairs, 1 pair/thread ----
            int pair = (task - N_T) * 256 + t;
            const int4* ep = (const int4*)edge_input + pair * 4;
            int4 a = ep[0], b = ep[1], c = ep[2], e4 = ep[3];
            uint4 r;
            r.x = ((unsigned)a.x  << 2) | ((unsigned)a.y  << 10) | ((unsigned)a.z  << 18) | ((unsigned)a.w  << 26);
            r.y = ((unsigned)b.x  << 2) | ((unsigned)b.y  << 10) | ((unsigned)b.z  << 18) | ((unsigned)b.w  << 26);
            r.z = ((unsigned)c.x  << 2) | ((unsigned)c.y  << 10) | ((unsigned)c.z  << 18) | ((unsigned)c.w  << 26);
            r.w = ((unsigned)e4.x << 2) | ((unsigned)e4.y << 10) | ((unsigned)e4.z << 18) | ((unsigned)e4.w << 26);
            g_packed[pair] = r;
            __threadfence();
            __syncthreads();
            if (t == 0) atomicAdd(&g_done, 1u);
        } else if (task < EDGE_BASE) {
            // ---- phi_spd: 512 pairs, 2 pairs/thread, STG.64 ----
            int pA = (task - SPD_BASE) * 512 + t * 2;
            int2 s = ((const int2*)spatial_pos)[pA >> 1];
#pragma unroll
            for (int k2 = 0; k2 < 16; ++k2) {
                float2 fa = __half22float2(shS[k2 * NSPAT + s.x]);
                float2 fb = __half22float2(shS[k2 * NSPAT + s.y]);
                *(float2*)(out + (2 * k2) * PAIRS + pA)     = make_float2(fa.x, fb.x);
                *(float2*)(out + (2 * k2 + 1) * PAIRS + pA) = make_float2(fa.y, fb.y);
            }
        } else {
            // ---- edge task: 256-pair tile x k-quarter (R12 verbatim) ----
            if (!staged) {
                if (t == 0) {
                    while (*(volatile unsigned*)&g_done < PREP_GATE)
                        __nanosleep(64);
                }
                __syncthreads();
                __threadfence();
                const float4* src = (const float4*)g_T2;
                float4* dst = (float4*)sh;
#pragma unroll
                for (int i = t; i < T2_ELEMS / 4; i += 256)
                    dst[i] = src[i];
                __syncthreads();
                staged = true;
            }

            int et   = task - EDGE_BASE;
            int tile = et >> 2;
            int kq   = et & 3;                  // 8 heads
            int pair = tile * 256 + t;

            uint4 pk4 = g_packed[pair];         // one LDG.128: 16 indices *4
            unsigned pk[4] = { pk4.x, pk4.y, pk4.z, pk4.w };
            int sp = __ldg(spatial_pos + pair);
            float rden = 1.0f / fmaxf((float)sp, 1.0f);

            float acc[8];
#pragma unroll
            for (int j = 0; j < 8; ++j) acc[j] = 0.0f;

#pragma unroll
            for (int g = 0; g < 4; ++g) {       // d-group of 4: d = 4g..4g+3
                const char* base = (const char*)(shT + ((4 * g) * 16 + kq * 4) * 32);
                unsigned o0 =  pk[g]        & 0xFCu;
                unsigned o1 = (pk[g] >> 8)  & 0xFCu;
                unsigned o2 = (pk[g] >> 16) & 0xFCu;
                unsigned o3 = (pk[g] >> 24);
                const __half2* p0 = (const __half2*)(base          + o0);
                const __half2* p1 = (const __half2*)(base + 2048   + o1);
                const __half2* p2 = (const __half2*)(base + 4096   + o2);
                const __half2* p3 = (const __half2*)(base + 6144   + o3);
#pragma unroll
                for (int j = 0; j < 4; ++j) {   // 4 k2 slots in this quarter
                    __half2 tt = __hadd2(__hadd2(p0[j * 32], p1[j * 32]),
                                         __hadd2(p2[j * 32], p3[j * 32]));
                    float2 f = __half22float2(tt);
                    acc[2 * j]     = fmaf(f.x, rden, acc[2 * j]);
                    acc[2 * j + 1] = fmaf(f.y, rden, acc[2 * j + 1]);
                }
            }

            float* oe = out + (H + kq * 8) * PAIRS + pair;
#pragma unroll
            for (int j = 0; j < 8; ++j)
                oe[j * PAIRS] = acc[j];
        }

        __syncthreads();       // publishes mail[slot]
        task = mail[slot];
        slot ^= 1;
    }

    // ---- exit: last block resets counters for the next graph replay ----
    __threadfence();
    __syncthreads();
    if (t == 0) {
        unsigned n = atomicAdd(&g_exit, 1u);
        if (n == GRID - 1) {
            g_task_counter = 0u;
            g_done = 0u;
            __threadfence();
            g_exit = 0u;
        }
    }
}

extern "C" void kernel_launch(void* const* d_in, const int* in_sizes, int n_in,
                              void* d_out, int out_size) {
    const int*   spatial_pos = nullptr;
    const int*   edge_input  = nullptr;
    const float* spd_table   = nullptr;
    const float* edge_table  = nullptr;
    const float* W           = nullptr;
    for (int i = 0; i < n_in; ++i) {
        switch (in_sizes[i]) {
            case PAIRS:          spatial_pos = (const int*)d_in[i];   break;
            case PAIRS * MAXD:   edge_input  = (const int*)d_in[i];   break;
            case NSPAT * H:      spd_table   = (const float*)d_in[i]; break;
            case H * H:          edge_table  = (const float*)d_in[i]; break;
            case NSPAT * H * H:  W           = (const float*)d_in[i]; break;
            default: break;
        }
    }

    cudaFuncSetAttribute(bond_all_kernel,
                         cudaFuncAttributeMaxDynamicSharedMemorySize, SMEM_BYTES);
    bond_all_kernel<<<GRID, 256, SMEM_BYTES>>>(
        spatial_pos, edge_input, spd_table, edge_table, W, (float*)d_out);
}